// round 17
// baseline (speedup 1.0000x reference)
#include <cuda_runtime.h>

// ---------------- problem constants ----------------
#define BATCH 1024
#define C0_ 512
#define C1_ 1024
#define K0_ 100
#define K1_ 50
#define KP0 128
#define KP1 64
#define ROWS0 (BATCH*C0_)   // 524288
#define ROWS1 (BATCH*C1_)   // 1048576

#define MB 16
#define CC 64
#define PITCH0 132
#define PITCH1 68
#define NT (BATCH/MB)       // 64 tiles per head
#define CS0 4               // head0 C-splits (128 chan each)
#define CS1 8               // head1 C-splits (128 chan each)
#define NGB (NT*CS0 + NT*CS1)   // 768 gemm blocks
#define NTILES (2*NT)       // 128

// ---------------- device state (zero-init; reset in-kernel for replay) -----
__device__ float    g_pooled0[ROWS0];
__device__ float    g_pooled1[ROWS1];
__device__ float    g_logits0[BATCH*K0_];
__device__ float    g_logits1[BATCH*K1_];
__device__ float    g_accum[4] = {0.f, 0.f, 0.f, 0.f};
__device__ unsigned g_tcnt[NTILES];
__device__ unsigned g_done = 0u;

// ---------------- fused pooling (R13 exact: proven) ----------------
#define NB0 ((ROWS0*32)/256)    // 65536
#define P1_RPB 128
#define P1_FLT (P1_RPB*49)      // 6272
#define P1_VEC (P1_FLT/4)       // 1568
#define NB1 (ROWS1/P1_RPB)      // 8192

__global__ void __launch_bounds__(256)
pool_kernel(const float* __restrict__ feat0, const float* __restrict__ feat1) {
    __shared__ float sf[P1_FLT];
    if (blockIdx.x == 0 && threadIdx.x < 5) {
        if (threadIdx.x < 4) g_accum[threadIdx.x] = 0.0f;
        else g_done = 0u;
    }
    if (blockIdx.x < NB0) {
        const unsigned wid  = (blockIdx.x * 256u + threadIdx.x) >> 5;
        const unsigned lane = threadIdx.x & 31u;
        const float4* src = reinterpret_cast<const float4*>(feat0) + (size_t)wid * 49;
        float4 a = __ldcs(src + lane);
        float  s = (a.x + a.y) + (a.z + a.w);
        if (lane < 17u) {
            float4 c = __ldcs(src + 32u + lane);
            s += (c.x + c.y) + (c.z + c.w);
        }
        #pragma unroll
        for (int o = 16; o; o >>= 1) s += __shfl_xor_sync(0xffffffffu, s, o);
        if (lane == 0u) g_pooled0[wid] = s * (1.0f / 196.0f);
    } else {
        const unsigned blk = blockIdx.x - NB0;
        const float4* src = reinterpret_cast<const float4*>(feat1) + (size_t)blk * P1_VEC;
        float4* dst = reinterpret_cast<float4*>(sf);
        #pragma unroll 4
        for (int i = threadIdx.x; i < P1_VEC; i += 256)
            dst[i] = __ldcs(src + i);
        __syncthreads();
        const int t = threadIdx.x;
        if (t < P1_RPB) {
            const float* r = sf + t * 49;
            float s0 = 0.f, s1 = 0.f, s2 = 0.f, s3 = 0.f;
            #pragma unroll
            for (int e = 0; e < 48; e += 4) {
                s0 += r[e]; s1 += r[e+1]; s2 += r[e+2]; s3 += r[e+3];
            }
            g_pooled1[(size_t)blk * P1_RPB + t] =
                ((s0 + s1) + (s2 + s3) + r[48]) * (1.0f / 49.0f);
        }
    }
}

// ---------------- split-C partial GEMM (R13-proven body) ----------------
template<int C, int K, int KPAD, int TK, int PITCH>
__device__ __forceinline__ void gemm_part(
    const float* __restrict__ pooled, const float* __restrict__ W,
    float* __restrict__ logits, int m0, int cbase, char* sraw)
{
    float (*sp)[CC]     = reinterpret_cast<float(*)[CC]>(sraw);
    float (*swt)[PITCH] = reinterpret_cast<float(*)[PITCH]>(sraw + 4*MB*CC);

    const int tid = threadIdx.x;
    const int ktg = tid & 63;
    const int bt  = tid >> 6;

    float acc[4][TK];
    #pragma unroll
    for (int j = 0; j < 4; j++)
        #pragma unroll
        for (int t = 0; t < TK; t++) acc[j][t] = 0.0f;

    #pragma unroll
    for (int cc0 = 0; cc0 < 128; cc0 += CC) {
        const int c0 = cbase + cc0;
        {
            const int row = tid >> 4;
            const int c4  = tid & 15;
            float4 v = *reinterpret_cast<const float4*>(
                pooled + (size_t)(m0 + row) * C + c0 + c4 * 4);
            *reinterpret_cast<float4*>(&sp[row][c4 * 4]) = v;
        }
        #pragma unroll
        for (int idx = tid; idx < KPAD * CC; idx += 256) {
            const int c = idx & (CC - 1);
            const int k = idx >> 6;
            swt[c][k] = (k < K) ? W[(size_t)k * C + c0 + c] : 0.0f;
        }
        __syncthreads();

        #pragma unroll 4
        for (int c4 = 0; c4 < CC / 4; c4++) {
            float pv[4][4];
            #pragma unroll
            for (int j = 0; j < 4; j++) {
                float4 v = *reinterpret_cast<const float4*>(&sp[bt * 4 + j][c4 * 4]);
                pv[j][0] = v.x; pv[j][1] = v.y; pv[j][2] = v.z; pv[j][3] = v.w;
            }
            #pragma unroll
            for (int cc = 0; cc < 4; cc++) {
                const int c = c4 * 4 + cc;
                if (TK == 2) {
                    float2 wv = *reinterpret_cast<const float2*>(&swt[c][ktg * 2]);
                    #pragma unroll
                    for (int j = 0; j < 4; j++) {
                        acc[j][0] = fmaf(pv[j][cc], wv.x, acc[j][0]);
                        acc[j][1] = fmaf(pv[j][cc], wv.y, acc[j][1]);
                    }
                } else {
                    float wv = swt[c][ktg];
                    #pragma unroll
                    for (int j = 0; j < 4; j++)
                        acc[j][0] = fmaf(pv[j][cc], wv, acc[j][0]);
                }
            }
        }
        __syncthreads();
    }

    #pragma unroll
    for (int t = 0; t < TK; t++) {
        const int k = ktg * TK + t;
        if (k < K) {
            #pragma unroll
            for (int j = 0; j < 4; j++)
                atomicAdd(&logits[(size_t)(m0 + bt * 4 + j) * K + k], acc[j][t]);
        }
    }
}

// ---------------- CE for one row (lean register footprint) -----------------
__device__ __forceinline__ void ce_row(
    float* __restrict__ logits, const float* __restrict__ bias, int K,
    const int* __restrict__ lut, const float* __restrict__ cw,
    const int* __restrict__ target, int b, int aoff)
{
    const int lane = threadIdx.x & 31;
    const int niter = (K + 31) >> 5;
    float m = -3.4e38f;
    #pragma unroll
    for (int i = 0; i < 4; i++) {
        if (i < niter) {
            const int k = lane + i * 32;
            if (k < K) m = fmaxf(m, __ldcg(&logits[(size_t)b * K + k]) + bias[k]);
        }
    }
    #pragma unroll
    for (int o = 16; o; o >>= 1) m = fmaxf(m, __shfl_xor_sync(0xffffffffu, m, o));
    float s = 0.0f;
    #pragma unroll
    for (int i = 0; i < 4; i++) {
        if (i < niter) {
            const int k = lane + i * 32;
            if (k < K) s += __expf(__ldcg(&logits[(size_t)b * K + k]) + bias[k] - m);
        }
    }
    #pragma unroll
    for (int o = 16; o; o >>= 1) s += __shfl_xor_sync(0xffffffffu, s, o);

    if (lane == 0) {
        const int t = lut[target[b]];
        const float tv  = __ldcg(&logits[(size_t)b * K + t]) + bias[t];
        const float nll = m + __logf(s) - tv;
        const float wt  = cw[t];
        atomicAdd(&g_accum[aoff],     wt * nll);
        atomicAdd(&g_accum[aoff + 1], wt);
    }
    __syncwarp();
    // reset logits for next graph replay
    #pragma unroll
    for (int i = 0; i < 4; i++) {
        if (i < niter) {
            const int k = lane + i * 32;
            if (k < K) logits[(size_t)b * K + k] = 0.0f;
        }
    }
}

// ---------------- gemm + fused per-tile CE + finalize ----------------------
__global__ void __launch_bounds__(256, 4)
gemm_ce_kernel(const float* __restrict__ W0, const float* __restrict__ W1,
               const float* __restrict__ b0v, const float* __restrict__ b1v,
               const int* __restrict__ lut0, const int* __restrict__ lut1,
               const float* __restrict__ cw0, const float* __restrict__ cw1,
               const int* __restrict__ target, float* __restrict__ out)
{
    __shared__ __align__(16) char sraw[4*MB*CC + 4*CC*PITCH0];   // 37888 B
    __shared__ unsigned s_last;
    const unsigned bx = blockIdx.x;
    const int tid = threadIdx.x;

    int tileid, nsplit, head;
    if (bx < NT * CS0) {
        const int tile = bx >> 2, cs = bx & 3;
        gemm_part<C0_, K0_, KP0, 2, PITCH0>(
            g_pooled0, W0, g_logits0, tile * MB, cs * 128, sraw);
        tileid = tile; nsplit = CS0; head = 0;
    } else {
        const unsigned q = bx - NT * CS0;
        const int tile = q >> 3, cs = q & 7;
        gemm_part<C1_, K1_, KP1, 1, PITCH1>(
            g_pooled1, W1, g_logits1, tile * MB, cs * 128, sraw);
        tileid = NT + tile; nsplit = CS1; head = 1;
    }

    // release: make this block's logit atomics visible, then bump tile counter
    __threadfence();
    __syncthreads();
    if (tid == 0) {
        const unsigned prev = atomicAdd(&g_tcnt[tileid], 1u);
        s_last = (prev == (unsigned)nsplit - 1u) ? 1u : 0u;
    }
    __syncthreads();

    if (s_last) {
        __threadfence();   // acquire: other splits' logits now visible (L2)
        const int m0 = (head ? (tileid - NT) : tileid) * MB;
        const int w = tid >> 5;
        #pragma unroll
        for (int j = 0; j < 2; j++) {
            const int r = m0 + w * 2 + j;
            if (head == 0) ce_row(g_logits0, b0v, K0_, lut0, cw0, target, r, 0);
            else           ce_row(g_logits1, b1v, K1_, lut1, cw1, target, r, 2);
        }
        __syncthreads();
        if (tid == 0) {
            atomicExch(&g_tcnt[tileid], 0u);   // reset for next replay
            __threadfence();
            const unsigned arrived = atomicAdd(&g_done, 1u);
            if (arrived == NTILES - 1u) {
                const float n0 = atomicAdd(&g_accum[0], 0.0f);
                const float d0 = atomicAdd(&g_accum[1], 0.0f);
                const float n1 = atomicAdd(&g_accum[2], 0.0f);
                const float d1 = atomicAdd(&g_accum[3], 0.0f);
                out[0] = n0 / d0 + n1 / d1;
                #pragma unroll
                for (int i = 0; i < 4; i++) atomicExch(&g_accum[i], 0.0f);
                __threadfence();
                atomicExch(&g_done, 0u);
            }
        }
    }
}

// ---------------- launch ----------------
extern "C" void kernel_launch(void* const* d_in, const int* in_sizes, int n_in,
                              void* d_out, int out_size) {
    (void)in_sizes; (void)n_in; (void)out_size;
    const float* feat0  = (const float*)d_in[0];
    const float* feat1  = (const float*)d_in[1];
    const float* W0     = (const float*)d_in[2];
    const float* b0v    = (const float*)d_in[3];
    const float* W1     = (const float*)d_in[4];
    const float* b1v    = (const float*)d_in[5];
    const int*   lut0   = (const int*)d_in[6];
    const int*   lut1   = (const int*)d_in[7];
    const float* cw0    = (const float*)d_in[8];
    const float* cw1    = (const float*)d_in[9];
    const int*   target = (const int*)d_in[10];
    float* out = (float*)d_out;

    pool_kernel<<<NB0 + NB1, 256>>>(feat0, feat1);
    gemm_ce_kernel<<<NGB, 256>>>(W0, W1, b0v, b1v, lut0, lut1,
                                 cw0, cw1, target, out);
}